// round 14
// baseline (speedup 1.0000x reference)
#include <cuda_runtime.h>
#include <cuda_bf16.h>
#include <math.h>

#define NN 50000
#define NE 800000
#define F1 128
#define C2 64
#define NG 512
#define NEG_SLOPE 0.2f
#define MAXDEG 96

typedef unsigned long long ull;
typedef unsigned int uint;

// ---------------- scratch ----------------
__device__ __align__(16) __nv_bfloat16 g_h1b[NN * F1];    // h1, bf16 only
__device__ __align__(16) __nv_bfloat16 g_out1b[NN * F1];  // layer1 out, bf16 only
__device__ __align__(16) __nv_bfloat16 g_h2b[NN * C2];    // h2, bf16 only
__device__ __align__(16) float g_as1[NN * 2], g_ad1[NN * 2];
__device__ __align__(16) float g_as2[NN], g_ad2[NN];
__device__ __align__(16) float g_pool[NG * C2];
__device__ __align__(16) float g_cnt[NG];
__device__ int g_deg[NN];
__device__ int g_slot[NN * MAXDEG];
__device__ int g_is64;

// ---------------- helpers ----------------
__device__ __forceinline__ float lrelu(float x) { return fmaxf(x, NEG_SLOPE * x); }
__device__ __forceinline__ float bflo(uint u) { return __uint_as_float(u << 16); }
__device__ __forceinline__ float bfhi(uint u) { return __uint_as_float(u & 0xFFFF0000u); }

__device__ __forceinline__ ull pack2(float x, float y) {
    ull r; asm("mov.b64 %0, {%1, %2};" : "=l"(r) : "f"(x), "f"(y)); return r;
}
__device__ __forceinline__ void unpack2(ull p, float& x, float& y) {
    asm("mov.b64 {%0, %1}, %2;" : "=f"(x), "=f"(y) : "l"(p));
}
__device__ __forceinline__ void ffma2(ull& acc, ull a, ull b) {
    asm("fma.rn.f32x2 %0, %1, %2, %0;" : "+l"(acc) : "l"(a), "l"(b));
}
// exact bf16x2 -> f32 pair
__device__ __forceinline__ ull bfpair(uint u) { return pack2(bflo(u), bfhi(u)); }
__device__ __forceinline__ void redv2(float* dst, float a, float b) {
    asm volatile("red.global.add.v2.f32 [%0], {%1, %2};"
                 :: "l"(dst), "f"(a), "f"(b) : "memory");
}
__device__ __forceinline__ long long loadIdx(const void* p, long long i, int is64) {
    if (is64) return ((const long long*)p)[i];
    return (long long)((const int*)p)[i];
}
__device__ __forceinline__ uint smem_u32(const void* p) {
    uint a;
    asm("{ .reg .u64 t; cvta.to.shared.u64 t, %1; cvt.u32.u64 %0, t; }" : "=r"(a) : "l"(p));
    return a;
}
__device__ __forceinline__ void ldmx4(uint* r, uint addr) {
    asm volatile("ldmatrix.sync.aligned.m8n8.x4.shared.b16 {%0,%1,%2,%3}, [%4];"
                 : "=r"(r[0]), "=r"(r[1]), "=r"(r[2]), "=r"(r[3]) : "r"(addr));
}
__device__ __forceinline__ void mma16816(float* d, const uint* a, uint b0, uint b1) {
    asm volatile(
        "mma.sync.aligned.m16n8k16.row.col.f32.bf16.bf16.f32 "
        "{%0,%1,%2,%3}, {%4,%5,%6,%7}, {%8,%9}, {%0,%1,%2,%3};"
        : "+f"(d[0]), "+f"(d[1]), "+f"(d[2]), "+f"(d[3])
        : "r"(a[0]), "r"(a[1]), "r"(a[2]), "r"(a[3]), "r"(b0), "r"(b1));
}

// ---------------- dtype detect only (buffers zeroed by memset nodes) ----------
__global__ void detect_k(const uint* __restrict__ ei) {
    __shared__ uint red;
    if (threadIdx.x == 0) red = 0u;
    __syncthreads();
    uint any = 0;
    for (int j = 1 + 2 * threadIdx.x; j < 4096; j += 512) any |= ei[j];
#pragma unroll
    for (int o = 16; o; o >>= 1) any |= __shfl_xor_sync(0xffffffffu, any, o);
    if ((threadIdx.x & 31) == 0) atomicOr(&red, any);
    __syncthreads();
    if (threadIdx.x == 0) g_is64 = (red == 0u) ? 1 : 0;
}

// ------- one-pass bucket scatter -------
__global__ void scatter_k(const void* __restrict__ ei) {
    int e = blockIdx.x * blockDim.x + threadIdx.x;
    if (e >= NE) return;
    int is64 = g_is64;
    int s = (int)loadIdx(ei, e, is64);
    int d = (int)loadIdx(ei, (long long)NE + e, is64);
    int pos = atomicAdd(&g_deg[d], 1);
    if (pos < MAXDEG) g_slot[d * MAXDEG + pos] = s;
}

// -------- mma.sync GEMM: (128 rows) @ (128 x NCOL), bf16 in, fused alpha -------
template <int NCOL, bool INBF16>
__device__ __forceinline__ void mma_gemm(const void* __restrict__ Ain,
                                         const float* __restrict__ W,
                                         __nv_bfloat16* __restrict__ Cb,
                                         const float* __restrict__ avs,
                                         const float* __restrict__ avd,
                                         float* __restrict__ as_out,
                                         float* __restrict__ ad_out) {
    constexpr int LD = 136;
    constexpr int WN = (NCOL == 128) ? 2 : 1;
    constexpr int MF = (NCOL == 128) ? 2 : 1;
    constexpr int HALF = NCOL / 2;
    extern __shared__ char smem[];
    __nv_bfloat16* As = (__nv_bfloat16*)smem;
    __nv_bfloat16* Bs = (__nv_bfloat16*)(smem + 128 * LD * 2);
    float* alphas = (float*)(smem + 128 * LD * 2 + NCOL * LD * 2);
    float* alphad = alphas + NCOL;
    const int tid = threadIdx.x, wid = tid >> 5, lane = tid & 31;
    const int row0 = blockIdx.x * 128;

    if (tid < NCOL) { alphas[tid] = avs[tid]; alphad[tid] = avd[tid]; }

    if (INBF16) {
        const __nv_bfloat16* A = (const __nv_bfloat16*)Ain;
        for (int i = tid; i < 128 * 16; i += 256) {
            int r = i >> 4, c8 = (i & 15) << 3;
            int gr = row0 + r;
            uint4 u = make_uint4(0u, 0u, 0u, 0u);
            if (gr < NN) u = *(const uint4*)(A + (size_t)gr * 128 + c8);
            *(uint4*)(As + r * LD + c8) = u;
        }
    } else {
        const float* A = (const float*)Ain;
        for (int i = tid; i < 128 * 32; i += 256) {
            int r = i >> 5, c4 = (i & 31) << 2;
            int gr = row0 + r;
            float4 v = make_float4(0.f, 0.f, 0.f, 0.f);
            if (gr < NN) v = *(const float4*)(A + (size_t)gr * 128 + c4);
            __nv_bfloat162 b0 = __floats2bfloat162_rn(v.x, v.y);
            __nv_bfloat162 b1 = __floats2bfloat162_rn(v.z, v.w);
            uint2 u; u.x = *(uint*)&b0; u.y = *(uint*)&b1;
            *(uint2*)(As + r * LD + c4) = u;
        }
    }
    for (int i = tid; i < 128 * (NCOL / 4); i += 256) {
        int k = i / (NCOL / 4), n4 = (i % (NCOL / 4)) * 4;
        float4 v = *(const float4*)(W + (size_t)k * NCOL + n4);
        Bs[(n4 + 0) * LD + k] = __float2bfloat16(v.x);
        Bs[(n4 + 1) * LD + k] = __float2bfloat16(v.y);
        Bs[(n4 + 2) * LD + k] = __float2bfloat16(v.z);
        Bs[(n4 + 3) * LD + k] = __float2bfloat16(v.w);
    }
    __syncthreads();

    const int warp_m = wid / WN, warp_n = wid % WN;
    const int m_base = warp_m * (MF * 16);
    const int n_base = warp_n * 64;
    const uint as_b = smem_u32(As), bs_b = smem_u32(Bs);

    float d[MF][8][4];
#pragma unroll
    for (int mf = 0; mf < MF; mf++)
#pragma unroll
        for (int nb = 0; nb < 8; nb++)
#pragma unroll
            for (int t = 0; t < 4; t++) d[mf][nb][t] = 0.f;

#pragma unroll
    for (int ks = 0; ks < 8; ks++) {
        uint a[MF][4];
#pragma unroll
        for (int mf = 0; mf < MF; mf++) {
            uint addr = as_b + (((m_base + mf * 16 + (lane & 15)) * LD) +
                                ks * 16 + ((lane >> 4) << 3)) * 2;
            ldmx4(a[mf], addr);
        }
        uint b[4][4];
#pragma unroll
        for (int nf = 0; nf < 4; nf++) {
            int nrow = n_base + nf * 16 + (lane & 7) + ((lane & 16) ? 8 : 0);
            int kcol = ks * 16 + ((lane & 8) ? 8 : 0);
            ldmx4(b[nf], bs_b + (nrow * LD + kcol) * 2);
        }
#pragma unroll
        for (int mf = 0; mf < MF; mf++)
#pragma unroll
            for (int nb = 0; nb < 8; nb++)
                mma16816(d[mf][nb], a[mf], b[nb >> 1][(nb & 1) * 2], b[nb >> 1][(nb & 1) * 2 + 1]);
    }

    __syncthreads();
#pragma unroll
    for (int mf = 0; mf < MF; mf++)
#pragma unroll
        for (int nb = 0; nb < 8; nb++) {
            int row = m_base + mf * 16 + (lane >> 2);
            int col = n_base + nb * 8 + (lane & 3) * 2;
            __nv_bfloat162 p0 = __floats2bfloat162_rn(d[mf][nb][0], d[mf][nb][1]);
            __nv_bfloat162 p1 = __floats2bfloat162_rn(d[mf][nb][2], d[mf][nb][3]);
            *(uint*)(As + row * LD + col) = *(uint*)&p0;
            *(uint*)(As + (row + 8) * LD + col) = *(uint*)&p1;
        }
    __syncthreads();

    int r = tid >> 1, hf = tid & 1;
    int gr = row0 + r;
    const __nv_bfloat16* crow = As + r * LD + hf * HALF;
    const float* As_ = alphas + hf * HALF;
    const float* Ad_ = alphad + hf * HALF;
    float ds = 0.f, dd = 0.f;
    bool ok = gr < NN;
#pragma unroll
    for (int c = 0; c < HALF; c += 8) {
        uint4 u = *(const uint4*)(crow + c);
        uint uu[4] = {u.x, u.y, u.z, u.w};
#pragma unroll
        for (int t = 0; t < 4; t++) {
            float f0 = bflo(uu[t]), f1 = bfhi(uu[t]);
            ds += f0 * As_[c + 2 * t] + f1 * As_[c + 2 * t + 1];
            dd += f0 * Ad_[c + 2 * t] + f1 * Ad_[c + 2 * t + 1];
        }
        if (ok) *(uint4*)(Cb + (size_t)gr * NCOL + hf * HALF + c) = u;
    }
    if (NCOL == 128) {
        if (ok) { as_out[gr * 2 + hf] = ds; ad_out[gr * 2 + hf] = dd; }
    } else {
        ds += __shfl_xor_sync(0xffffffffu, ds, 1);
        dd += __shfl_xor_sync(0xffffffffu, dd, 1);
        if (ok && hf == 0) { as_out[gr] = ds; ad_out[gr] = dd; }
    }
}

__global__ void __launch_bounds__(256) gemm1_k(const float* __restrict__ A,
                                               const float* __restrict__ W,
                                               const float* __restrict__ avs,
                                               const float* __restrict__ avd) {
    mma_gemm<128, false>(A, W, g_h1b, avs, avd, g_as1, g_ad1);
}
__global__ void __launch_bounds__(256) gemm2_k(const float* __restrict__ W,
                                               const float* __restrict__ avs,
                                               const float* __restrict__ avd) {
    mma_gemm<64, true>(g_out1b, W, g_h2b, avs, avd, g_as2, g_ad2);
}

// ------- layer 1: coef pass + 2-edges-per-warp f32x2 gather (deep pipeline) ----
__global__ void __launch_bounds__(256) edge1_k(const float* __restrict__ b1) {
    __shared__ float4 sc[8][MAXDEG];   // (c0,c0,c1,c1) per edge
    __shared__ int soff[8][MAXDEG];
    const int wslot = threadIdx.x >> 5;
    int d = (blockIdx.x * blockDim.x + threadIdx.x) >> 5;
    int lane = threadIdx.x & 31;
    if (d >= NN) return;
    int deg = g_deg[d];
    if (deg > MAXDEG) deg = MAXDEG;
    const int* slots = g_slot + d * MAXDEG;
    float2 adp = *(const float2*)(g_ad1 + d * 2);

    float s0 = 0.f, s1 = 0.f;
    for (int j = lane; j < deg; j += 32) {
        int s = slots[j];
        float2 a = *(const float2*)(g_as1 + s * 2);
        float c0 = __expf(lrelu(a.x + adp.x));
        float c1 = __expf(lrelu(a.y + adp.y));
        sc[wslot][j] = make_float4(c0, c0, c1, c1);
        soff[wslot][j] = s << 8;
        s0 += c0; s1 += c1;
    }
#pragma unroll
    for (int o = 16; o; o >>= 1) {
        s0 += __shfl_xor_sync(0xffffffffu, s0, o);
        s1 += __shfl_xor_sync(0xffffffffu, s1, o);
    }
    float2 asd = *(const float2*)(g_as1 + d * 2);
    float cs0 = __expf(lrelu(asd.x + adp.x));
    float cs1 = __expf(lrelu(asd.y + adp.y));
    s0 += cs0; s1 += cs1;
    __syncwarp();

    const int half = lane >> 4, l = lane & 15;
    const int hd = l >> 3;
    const char* base = (const char*)g_h1b + l * 16;
    const ull* cpp = (const ull*)&sc[wslot][0] + hd;
    const int* offp = &soff[wslot][0];

    ull acc[4] = {0ull, 0ull, 0ull, 0ull};
    if (half == 0) {
        uint4 u = *(const uint4*)(base + ((size_t)(uint)d << 8));
        float c = hd ? cs1 : cs0;
        ull cpk = pack2(c, c);
        ffma2(acc[0], bfpair(u.x), cpk);
        ffma2(acc[1], bfpair(u.y), cpk);
        ffma2(acc[2], bfpair(u.z), cpk);
        ffma2(acc[3], bfpair(u.w), cpk);
    }
#pragma unroll 8
    for (int j = half; j < deg; j += 2) {
        ull cpk = cpp[2 * j];
        int off = offp[j];
        uint4 u = *(const uint4*)(base + off);
        ffma2(acc[0], bfpair(u.x), cpk);
        ffma2(acc[1], bfpair(u.y), cpk);
        ffma2(acc[2], bfpair(u.z), cpk);
        ffma2(acc[3], bfpair(u.w), cpk);
    }
    float av[8];
#pragma unroll
    for (int t = 0; t < 4; t++) unpack2(acc[t], av[2 * t], av[2 * t + 1]);
#pragma unroll
    for (int t = 0; t < 8; t++) av[t] += __shfl_xor_sync(0xffffffffu, av[t], 16);

    float inv = 1.f / (hd ? s1 : s0);
    int col0 = l * 8 + half * 4;
    float4 b = *(const float4*)(b1 + col0);
    float r0 = fmaxf(av[half * 4 + 0] * inv + b.x, 0.f);
    float r1 = fmaxf(av[half * 4 + 1] * inv + b.y, 0.f);
    float r2 = fmaxf(av[half * 4 + 2] * inv + b.z, 0.f);
    float r3 = fmaxf(av[half * 4 + 3] * inv + b.w, 0.f);
    __nv_bfloat162 o0 = __floats2bfloat162_rn(r0, r1);
    __nv_bfloat162 o1 = __floats2bfloat162_rn(r2, r3);
    uint2 ov; ov.x = *(uint*)&o0; ov.y = *(uint*)&o1;
    *(uint2*)(g_out1b + (size_t)d * 128 + col0) = ov;
}

// ------- layer 2: same structure + direct pooling -------------------------------
__global__ void __launch_bounds__(256) edge2_k(const float* __restrict__ b2,
                                               const void* __restrict__ batch) {
    __shared__ float2 sc[8][MAXDEG];
    __shared__ int soff[8][MAXDEG];
    const int wslot = threadIdx.x >> 5;
    int d = (blockIdx.x * blockDim.x + threadIdx.x) >> 5;
    int lane = threadIdx.x & 31;
    if (d >= NN) return;
    int deg = g_deg[d];
    if (deg > MAXDEG) deg = MAXDEG;
    const int* slots = g_slot + d * MAXDEG;
    float ad = g_ad2[d];

    float sum = 0.f;
    for (int j = lane; j < deg; j += 32) {
        int s = slots[j];
        float c = __expf(lrelu(g_as2[s] + ad));
        sc[wslot][j] = make_float2(c, c);
        soff[wslot][j] = s << 7;
        sum += c;
    }
#pragma unroll
    for (int o = 16; o; o >>= 1) sum += __shfl_xor_sync(0xffffffffu, sum, o);
    float csf = __expf(lrelu(g_as2[d] + ad));
    sum += csf;
    __syncwarp();

    const int half = lane >> 4, l = lane & 15;
    const char* base = (const char*)g_h2b + l * 8;
    const ull* cpp = (const ull*)&sc[wslot][0];
    const int* offp = &soff[wslot][0];

    ull acc[2] = {0ull, 0ull};
    if (half == 0) {
        uint2 u = *(const uint2*)(base + ((size_t)(uint)d << 7));
        ull cpk = pack2(csf, csf);
        ffma2(acc[0], bfpair(u.x), cpk);
        ffma2(acc[1], bfpair(u.y), cpk);
    }
#pragma unroll 8
    for (int j = half; j < deg; j += 2) {
        ull cpk = cpp[j];
        int off = offp[j];
        uint2 u = *(const uint2*)(base + off);
        ffma2(acc[0], bfpair(u.x), cpk);
        ffma2(acc[1], bfpair(u.y), cpk);
    }
    float av[4];
    unpack2(acc[0], av[0], av[1]);
    unpack2(acc[1], av[2], av[3]);
#pragma unroll
    for (int t = 0; t < 4; t++) av[t] += __shfl_xor_sync(0xffffffffu, av[t], 16);

    float inv = 1.f / sum;
    int col0 = l * 4 + half * 2;
    float r0 = fmaxf(av[half * 2 + 0] * inv + b2[col0], 0.f);
    float r1 = fmaxf(av[half * 2 + 1] * inv + b2[col0 + 1], 0.f);

    int bg = (int)loadIdx(batch, d, g_is64);
    redv2(g_pool + (size_t)bg * 64 + col0, r0, r1);
    if (!lane) atomicAdd(g_cnt + bg, 1.f);
}

// ---------------- final FC + log_softmax ----------------
__global__ void final_k(const float* __restrict__ fcW, const float* __restrict__ fcb,
                        float* __restrict__ out) {
    int gw = (blockIdx.x * blockDim.x + threadIdx.x) >> 5;
    int lane = threadIdx.x & 31;
    if (gw >= NG) return;
    float inv = 1.f / fmaxf(g_cnt[gw], 1.f);
    float p0 = g_pool[(size_t)gw * 64 + lane] * inv;
    float p1 = g_pool[(size_t)gw * 64 + 32 + lane] * inv;
    float l0 = p0 * fcW[lane * 2] + p1 * fcW[(lane + 32) * 2];
    float l1 = p0 * fcW[lane * 2 + 1] + p1 * fcW[(lane + 32) * 2 + 1];
#pragma unroll
    for (int o = 16; o; o >>= 1) {
        l0 += __shfl_xor_sync(0xffffffffu, l0, o);
        l1 += __shfl_xor_sync(0xffffffffu, l1, o);
    }
    if (!lane) {
        l0 += fcb[0];
        l1 += fcb[1];
        float m = fmaxf(l0, l1);
        float lse = m + logf(expf(l0 - m) + expf(l1 - m));
        out[gw * 2] = l0 - lse;
        out[gw * 2 + 1] = l1 - lse;
    }
}

// ---------------- launch ----------------
extern "C" void kernel_launch(void* const* d_in, const int* in_sizes, int n_in,
                              void* d_out, int out_size) {
    const float* x = (const float*)d_in[0];
    const void* ei = d_in[1];
    const void* batch = d_in[2];
    const float* W1 = (const float*)d_in[3];
    const float* asrc1 = (const float*)d_in[4];
    const float* adst1 = (const float*)d_in[5];
    const float* b1 = (const float*)d_in[6];
    const float* W2 = (const float*)d_in[7];
    const float* asrc2 = (const float*)d_in[8];
    const float* adst2 = (const float*)d_in[9];
    const float* b2 = (const float*)d_in[10];
    const float* fcW = (const float*)d_in[11];
    const float* fcb = (const float*)d_in[12];
    float* out = (float*)d_out;

    const int SMEM1 = 128 * 136 * 2 + 128 * 136 * 2 + 128 * 2 * 4;  // 70656
    const int SMEM2 = 128 * 136 * 2 + 64 * 136 * 2 + 64 * 2 * 4;    // 52736

    static cudaStream_t s2 = nullptr;
    static cudaEvent_t evA = nullptr, evB = nullptr;
    static void *p_deg = nullptr, *p_pool = nullptr, *p_cnt = nullptr;
    if (!s2) {
        cudaStreamCreateWithFlags(&s2, cudaStreamNonBlocking);
        cudaEventCreateWithFlags(&evA, cudaEventDisableTiming);
        cudaEventCreateWithFlags(&evB, cudaEventDisableTiming);
        cudaFuncSetAttribute(gemm1_k, cudaFuncAttributeMaxDynamicSharedMemorySize, SMEM1);
        cudaFuncSetAttribute(gemm2_k, cudaFuncAttributeMaxDynamicSharedMemorySize, SMEM2);
        cudaGetSymbolAddress(&p_deg, g_deg);
        cudaGetSymbolAddress(&p_pool, g_pool);
        cudaGetSymbolAddress(&p_cnt, g_cnt);
    }

    // fork: bucket build (+zero-fills) on s2, gemm1 on main stream
    cudaEventRecord(evA, 0);
    cudaStreamWaitEvent(s2, evA, 0);

    cudaMemsetAsync(p_deg, 0, NN * sizeof(int), s2);
    cudaMemsetAsync(p_pool, 0, NG * C2 * sizeof(float), s2);
    cudaMemsetAsync(p_cnt, 0, NG * sizeof(float), s2);
    detect_k<<<1, 512, 0, s2>>>((const uint*)ei);
    scatter_k<<<(NE + 255) / 256, 256, 0, s2>>>(ei);
    cudaEventRecord(evB, s2);

    gemm1_k<<<(NN + 127) / 128, 256, SMEM1>>>(x, W1, asrc1, adst1);

    cudaStreamWaitEvent(0, evB, 0);

    edge1_k<<<(NN * 32 + 255) / 256, 256>>>(b1);
    gemm2_k<<<(NN + 127) / 128, 256, SMEM2>>>(W2, asrc2, adst2);
    edge2_k<<<(NN * 32 + 255) / 256, 256>>>(b2, batch);
    final_k<<<(NG * 32 + 255) / 256, 256>>>(fcW, fcb, out);
}

// round 15
// speedup vs baseline: 1.0226x; 1.0226x over previous
#include <cuda_runtime.h>
#include <cuda_bf16.h>
#include <math.h>

#define NN 50000
#define NE 800000
#define F1 128
#define C2 64
#define NG 512
#define NEG_SLOPE 0.2f
#define MAXDEG 96

typedef unsigned long long ull;
typedef unsigned int uint;

// ---------------- scratch ----------------
__device__ __align__(16) __nv_bfloat16 g_h1b[NN * F1];    // h1, bf16 only
__device__ __align__(16) __nv_bfloat16 g_out1b[NN * F1];  // layer1 out, bf16 only
__device__ __align__(16) __nv_bfloat16 g_h2b[NN * C2];    // h2, bf16 only
__device__ __align__(16) float g_as1[NN * 2], g_ad1[NN * 2];
__device__ __align__(16) float g_as2[NN], g_ad2[NN];
__device__ __align__(16) float g_pool[NG * C2];
__device__ __align__(16) float g_cnt[NG];
__device__ int g_deg[NN];
__device__ int g_slot[NN * MAXDEG];
__device__ int g_is64;

// ---------------- helpers ----------------
__device__ __forceinline__ float lrelu(float x) { return fmaxf(x, NEG_SLOPE * x); }
__device__ __forceinline__ float bflo(uint u) { return __uint_as_float(u << 16); }
__device__ __forceinline__ float bfhi(uint u) { return __uint_as_float(u & 0xFFFF0000u); }

__device__ __forceinline__ ull pack2(float x, float y) {
    ull r; asm("mov.b64 %0, {%1, %2};" : "=l"(r) : "f"(x), "f"(y)); return r;
}
__device__ __forceinline__ void unpack2(ull p, float& x, float& y) {
    asm("mov.b64 {%0, %1}, %2;" : "=f"(x), "=f"(y) : "l"(p));
}
__device__ __forceinline__ void ffma2(ull& acc, ull a, ull b) {
    asm("fma.rn.f32x2 %0, %1, %2, %0;" : "+l"(acc) : "l"(a), "l"(b));
}
// exact bf16x2 -> f32 pair
__device__ __forceinline__ ull bfpair(uint u) { return pack2(bflo(u), bfhi(u)); }
__device__ __forceinline__ void redv2(float* dst, float a, float b) {
    asm volatile("red.global.add.v2.f32 [%0], {%1, %2};"
                 :: "l"(dst), "f"(a), "f"(b) : "memory");
}
__device__ __forceinline__ long long loadIdx(const void* p, long long i, int is64) {
    if (is64) return ((const long long*)p)[i];
    return (long long)((const int*)p)[i];
}
__device__ __forceinline__ uint smem_u32(const void* p) {
    uint a;
    asm("{ .reg .u64 t; cvta.to.shared.u64 t, %1; cvt.u32.u64 %0, t; }" : "=r"(a) : "l"(p));
    return a;
}
__device__ __forceinline__ void ldmx4(uint* r, uint addr) {
    asm volatile("ldmatrix.sync.aligned.m8n8.x4.shared.b16 {%0,%1,%2,%3}, [%4];"
                 : "=r"(r[0]), "=r"(r[1]), "=r"(r[2]), "=r"(r[3]) : "r"(addr));
}
__device__ __forceinline__ void mma16816(float* d, const uint* a, uint b0, uint b1) {
    asm volatile(
        "mma.sync.aligned.m16n8k16.row.col.f32.bf16.bf16.f32 "
        "{%0,%1,%2,%3}, {%4,%5,%6,%7}, {%8,%9}, {%0,%1,%2,%3};"
        : "+f"(d[0]), "+f"(d[1]), "+f"(d[2]), "+f"(d[3])
        : "r"(a[0]), "r"(a[1]), "r"(a[2]), "r"(a[3]), "r"(b0), "r"(b1));
}

// ---------------- dtype detect only (buffers zeroed by memset nodes) ----------
__global__ void detect_k(const uint* __restrict__ ei) {
    __shared__ uint red;
    if (threadIdx.x == 0) red = 0u;
    __syncthreads();
    uint any = 0;
    for (int j = 1 + 2 * threadIdx.x; j < 4096; j += 512) any |= ei[j];
#pragma unroll
    for (int o = 16; o; o >>= 1) any |= __shfl_xor_sync(0xffffffffu, any, o);
    if ((threadIdx.x & 31) == 0) atomicOr(&red, any);
    __syncthreads();
    if (threadIdx.x == 0) g_is64 = (red == 0u) ? 1 : 0;
}

// ------- one-pass bucket scatter -------
__global__ void scatter_k(const void* __restrict__ ei) {
    int e = blockIdx.x * blockDim.x + threadIdx.x;
    if (e >= NE) return;
    int is64 = g_is64;
    int s = (int)loadIdx(ei, e, is64);
    int d = (int)loadIdx(ei, (long long)NE + e, is64);
    int pos = atomicAdd(&g_deg[d], 1);
    if (pos < MAXDEG) g_slot[d * MAXDEG + pos] = s;
}

// -------- mma.sync GEMM: (128 rows) @ (128 x NCOL), bf16 in, fused alpha -------
template <int NCOL, bool INBF16>
__device__ __forceinline__ void mma_gemm(const void* __restrict__ Ain,
                                         const float* __restrict__ W,
                                         __nv_bfloat16* __restrict__ Cb,
                                         const float* __restrict__ avs,
                                         const float* __restrict__ avd,
                                         float* __restrict__ as_out,
                                         float* __restrict__ ad_out) {
    constexpr int LD = 136;
    constexpr int WN = (NCOL == 128) ? 2 : 1;
    constexpr int MF = (NCOL == 128) ? 2 : 1;
    constexpr int HALF = NCOL / 2;
    extern __shared__ char smem[];
    __nv_bfloat16* As = (__nv_bfloat16*)smem;
    __nv_bfloat16* Bs = (__nv_bfloat16*)(smem + 128 * LD * 2);
    float* alphas = (float*)(smem + 128 * LD * 2 + NCOL * LD * 2);
    float* alphad = alphas + NCOL;
    const int tid = threadIdx.x, wid = tid >> 5, lane = tid & 31;
    const int row0 = blockIdx.x * 128;

    if (tid < NCOL) { alphas[tid] = avs[tid]; alphad[tid] = avd[tid]; }

    if (INBF16) {
        const __nv_bfloat16* A = (const __nv_bfloat16*)Ain;
        for (int i = tid; i < 128 * 16; i += 256) {
            int r = i >> 4, c8 = (i & 15) << 3;
            int gr = row0 + r;
            uint4 u = make_uint4(0u, 0u, 0u, 0u);
            if (gr < NN) u = *(const uint4*)(A + (size_t)gr * 128 + c8);
            *(uint4*)(As + r * LD + c8) = u;
        }
    } else {
        const float* A = (const float*)Ain;
        for (int i = tid; i < 128 * 32; i += 256) {
            int r = i >> 5, c4 = (i & 31) << 2;
            int gr = row0 + r;
            float4 v = make_float4(0.f, 0.f, 0.f, 0.f);
            if (gr < NN) v = *(const float4*)(A + (size_t)gr * 128 + c4);
            __nv_bfloat162 b0 = __floats2bfloat162_rn(v.x, v.y);
            __nv_bfloat162 b1 = __floats2bfloat162_rn(v.z, v.w);
            uint2 u; u.x = *(uint*)&b0; u.y = *(uint*)&b1;
            *(uint2*)(As + r * LD + c4) = u;
        }
    }
    for (int i = tid; i < 128 * (NCOL / 4); i += 256) {
        int k = i / (NCOL / 4), n4 = (i % (NCOL / 4)) * 4;
        float4 v = *(const float4*)(W + (size_t)k * NCOL + n4);
        Bs[(n4 + 0) * LD + k] = __float2bfloat16(v.x);
        Bs[(n4 + 1) * LD + k] = __float2bfloat16(v.y);
        Bs[(n4 + 2) * LD + k] = __float2bfloat16(v.z);
        Bs[(n4 + 3) * LD + k] = __float2bfloat16(v.w);
    }
    __syncthreads();

    const int warp_m = wid / WN, warp_n = wid % WN;
    const int m_base = warp_m * (MF * 16);
    const int n_base = warp_n * 64;
    const uint as_b = smem_u32(As), bs_b = smem_u32(Bs);

    float d[MF][8][4];
#pragma unroll
    for (int mf = 0; mf < MF; mf++)
#pragma unroll
        for (int nb = 0; nb < 8; nb++)
#pragma unroll
            for (int t = 0; t < 4; t++) d[mf][nb][t] = 0.f;

#pragma unroll
    for (int ks = 0; ks < 8; ks++) {
        uint a[MF][4];
#pragma unroll
        for (int mf = 0; mf < MF; mf++) {
            uint addr = as_b + (((m_base + mf * 16 + (lane & 15)) * LD) +
                                ks * 16 + ((lane >> 4) << 3)) * 2;
            ldmx4(a[mf], addr);
        }
        uint b[4][4];
#pragma unroll
        for (int nf = 0; nf < 4; nf++) {
            int nrow = n_base + nf * 16 + (lane & 7) + ((lane & 16) ? 8 : 0);
            int kcol = ks * 16 + ((lane & 8) ? 8 : 0);
            ldmx4(b[nf], bs_b + (nrow * LD + kcol) * 2);
        }
#pragma unroll
        for (int mf = 0; mf < MF; mf++)
#pragma unroll
            for (int nb = 0; nb < 8; nb++)
                mma16816(d[mf][nb], a[mf], b[nb >> 1][(nb & 1) * 2], b[nb >> 1][(nb & 1) * 2 + 1]);
    }

    __syncthreads();
#pragma unroll
    for (int mf = 0; mf < MF; mf++)
#pragma unroll
        for (int nb = 0; nb < 8; nb++) {
            int row = m_base + mf * 16 + (lane >> 2);
            int col = n_base + nb * 8 + (lane & 3) * 2;
            __nv_bfloat162 p0 = __floats2bfloat162_rn(d[mf][nb][0], d[mf][nb][1]);
            __nv_bfloat162 p1 = __floats2bfloat162_rn(d[mf][nb][2], d[mf][nb][3]);
            *(uint*)(As + row * LD + col) = *(uint*)&p0;
            *(uint*)(As + (row + 8) * LD + col) = *(uint*)&p1;
        }
    __syncthreads();

    int r = tid >> 1, hf = tid & 1;
    int gr = row0 + r;
    const __nv_bfloat16* crow = As + r * LD + hf * HALF;
    const float* As_ = alphas + hf * HALF;
    const float* Ad_ = alphad + hf * HALF;
    float ds = 0.f, dd = 0.f;
    bool ok = gr < NN;
#pragma unroll
    for (int c = 0; c < HALF; c += 8) {
        uint4 u = *(const uint4*)(crow + c);
        uint uu[4] = {u.x, u.y, u.z, u.w};
#pragma unroll
        for (int t = 0; t < 4; t++) {
            float f0 = bflo(uu[t]), f1 = bfhi(uu[t]);
            ds += f0 * As_[c + 2 * t] + f1 * As_[c + 2 * t + 1];
            dd += f0 * Ad_[c + 2 * t] + f1 * Ad_[c + 2 * t + 1];
        }
        if (ok) *(uint4*)(Cb + (size_t)gr * NCOL + hf * HALF + c) = u;
    }
    if (NCOL == 128) {
        if (ok) { as_out[gr * 2 + hf] = ds; ad_out[gr * 2 + hf] = dd; }
    } else {
        ds += __shfl_xor_sync(0xffffffffu, ds, 1);
        dd += __shfl_xor_sync(0xffffffffu, dd, 1);
        if (ok && hf == 0) { as_out[gr] = ds; ad_out[gr] = dd; }
    }
}

__global__ void __launch_bounds__(256) gemm1_k(const float* __restrict__ A,
                                               const float* __restrict__ W,
                                               const float* __restrict__ avs,
                                               const float* __restrict__ avd) {
    mma_gemm<128, false>(A, W, g_h1b, avs, avd, g_as1, g_ad1);
}
__global__ void __launch_bounds__(256) gemm2_k(const float* __restrict__ W,
                                               const float* __restrict__ avs,
                                               const float* __restrict__ avd) {
    mma_gemm<64, true>(g_out1b, W, g_h2b, avs, avd, g_as2, g_ad2);
}

// ------- layer 1: coef pass + 2-edges-per-warp f32x2 gather --------------------
__global__ void __launch_bounds__(256) edge1_k(const float* __restrict__ b1) {
    __shared__ float4 sc[8][MAXDEG];   // (c0,c0,c1,c1) per edge
    __shared__ int soff[8][MAXDEG];
    const int wslot = threadIdx.x >> 5;
    int d = (blockIdx.x * blockDim.x + threadIdx.x) >> 5;
    int lane = threadIdx.x & 31;
    if (d >= NN) return;
    int deg = g_deg[d];
    if (deg > MAXDEG) deg = MAXDEG;
    const int* slots = g_slot + d * MAXDEG;
    float2 adp = *(const float2*)(g_ad1 + d * 2);

    float s0 = 0.f, s1 = 0.f;
    for (int j = lane; j < deg; j += 32) {
        int s = slots[j];
        float2 a = *(const float2*)(g_as1 + s * 2);
        float c0 = __expf(lrelu(a.x + adp.x));
        float c1 = __expf(lrelu(a.y + adp.y));
        sc[wslot][j] = make_float4(c0, c0, c1, c1);
        soff[wslot][j] = s << 8;
        s0 += c0; s1 += c1;
    }
#pragma unroll
    for (int o = 16; o; o >>= 1) {
        s0 += __shfl_xor_sync(0xffffffffu, s0, o);
        s1 += __shfl_xor_sync(0xffffffffu, s1, o);
    }
    float2 asd = *(const float2*)(g_as1 + d * 2);
    float cs0 = __expf(lrelu(asd.x + adp.x));
    float cs1 = __expf(lrelu(asd.y + adp.y));
    s0 += cs0; s1 += cs1;
    __syncwarp();

    const int half = lane >> 4, l = lane & 15;
    const int hd = l >> 3;
    const char* base = (const char*)g_h1b + l * 16;
    const ull* cpp = (const ull*)&sc[wslot][0] + hd;
    const int* offp = &soff[wslot][0];

    ull acc[4] = {0ull, 0ull, 0ull, 0ull};
    if (half == 0) {
        uint4 u = *(const uint4*)(base + ((size_t)(uint)d << 8));
        float c = hd ? cs1 : cs0;
        ull cpk = pack2(c, c);
        ffma2(acc[0], bfpair(u.x), cpk);
        ffma2(acc[1], bfpair(u.y), cpk);
        ffma2(acc[2], bfpair(u.z), cpk);
        ffma2(acc[3], bfpair(u.w), cpk);
    }
#pragma unroll 2
    for (int j = half; j < deg; j += 2) {
        ull cpk = cpp[2 * j];
        int off = offp[j];
        uint4 u = *(const uint4*)(base + off);
        ffma2(acc[0], bfpair(u.x), cpk);
        ffma2(acc[1], bfpair(u.y), cpk);
        ffma2(acc[2], bfpair(u.z), cpk);
        ffma2(acc[3], bfpair(u.w), cpk);
    }
    float av[8];
#pragma unroll
    for (int t = 0; t < 4; t++) unpack2(acc[t], av[2 * t], av[2 * t + 1]);
#pragma unroll
    for (int t = 0; t < 8; t++) av[t] += __shfl_xor_sync(0xffffffffu, av[t], 16);

    float inv = 1.f / (hd ? s1 : s0);
    int col0 = l * 8 + half * 4;
    float4 b = *(const float4*)(b1 + col0);
    float r0 = fmaxf(av[half * 4 + 0] * inv + b.x, 0.f);
    float r1 = fmaxf(av[half * 4 + 1] * inv + b.y, 0.f);
    float r2 = fmaxf(av[half * 4 + 2] * inv + b.z, 0.f);
    float r3 = fmaxf(av[half * 4 + 3] * inv + b.w, 0.f);
    __nv_bfloat162 o0 = __floats2bfloat162_rn(r0, r1);
    __nv_bfloat162 o1 = __floats2bfloat162_rn(r2, r3);
    uint2 ov; ov.x = *(uint*)&o0; ov.y = *(uint*)&o1;
    *(uint2*)(g_out1b + (size_t)d * 128 + col0) = ov;
}

// ------- layer 2: same structure + direct pooling -------------------------------
__global__ void __launch_bounds__(256) edge2_k(const float* __restrict__ b2,
                                               const void* __restrict__ batch) {
    __shared__ float2 sc[8][MAXDEG];
    __shared__ int soff[8][MAXDEG];
    const int wslot = threadIdx.x >> 5;
    int d = (blockIdx.x * blockDim.x + threadIdx.x) >> 5;
    int lane = threadIdx.x & 31;
    if (d >= NN) return;
    int deg = g_deg[d];
    if (deg > MAXDEG) deg = MAXDEG;
    const int* slots = g_slot + d * MAXDEG;
    float ad = g_ad2[d];

    float sum = 0.f;
    for (int j = lane; j < deg; j += 32) {
        int s = slots[j];
        float c = __expf(lrelu(g_as2[s] + ad));
        sc[wslot][j] = make_float2(c, c);
        soff[wslot][j] = s << 7;
        sum += c;
    }
#pragma unroll
    for (int o = 16; o; o >>= 1) sum += __shfl_xor_sync(0xffffffffu, sum, o);
    float csf = __expf(lrelu(g_as2[d] + ad));
    sum += csf;
    __syncwarp();

    const int half = lane >> 4, l = lane & 15;
    const char* base = (const char*)g_h2b + l * 8;
    const ull* cpp = (const ull*)&sc[wslot][0];
    const int* offp = &soff[wslot][0];

    ull acc[2] = {0ull, 0ull};
    if (half == 0) {
        uint2 u = *(const uint2*)(base + ((size_t)(uint)d << 7));
        ull cpk = pack2(csf, csf);
        ffma2(acc[0], bfpair(u.x), cpk);
        ffma2(acc[1], bfpair(u.y), cpk);
    }
#pragma unroll 2
    for (int j = half; j < deg; j += 2) {
        ull cpk = cpp[j];
        int off = offp[j];
        uint2 u = *(const uint2*)(base + off);
        ffma2(acc[0], bfpair(u.x), cpk);
        ffma2(acc[1], bfpair(u.y), cpk);
    }
    float av[4];
    unpack2(acc[0], av[0], av[1]);
    unpack2(acc[1], av[2], av[3]);
#pragma unroll
    for (int t = 0; t < 4; t++) av[t] += __shfl_xor_sync(0xffffffffu, av[t], 16);

    float inv = 1.f / sum;
    int col0 = l * 4 + half * 2;
    float r0 = fmaxf(av[half * 2 + 0] * inv + b2[col0], 0.f);
    float r1 = fmaxf(av[half * 2 + 1] * inv + b2[col0 + 1], 0.f);

    int bg = (int)loadIdx(batch, d, g_is64);
    redv2(g_pool + (size_t)bg * 64 + col0, r0, r1);
    if (!lane) atomicAdd(g_cnt + bg, 1.f);
}

// ---------------- final FC + log_softmax ----------------
__global__ void final_k(const float* __restrict__ fcW, const float* __restrict__ fcb,
                        float* __restrict__ out) {
    int gw = (blockIdx.x * blockDim.x + threadIdx.x) >> 5;
    int lane = threadIdx.x & 31;
    if (gw >= NG) return;
    float inv = 1.f / fmaxf(g_cnt[gw], 1.f);
    float p0 = g_pool[(size_t)gw * 64 + lane] * inv;
    float p1 = g_pool[(size_t)gw * 64 + 32 + lane] * inv;
    float l0 = p0 * fcW[lane * 2] + p1 * fcW[(lane + 32) * 2];
    float l1 = p0 * fcW[lane * 2 + 1] + p1 * fcW[(lane + 32) * 2 + 1];
#pragma unroll
    for (int o = 16; o; o >>= 1) {
        l0 += __shfl_xor_sync(0xffffffffu, l0, o);
        l1 += __shfl_xor_sync(0xffffffffu, l1, o);
    }
    if (!lane) {
        l0 += fcb[0];
        l1 += fcb[1];
        float m = fmaxf(l0, l1);
        float lse = m + logf(expf(l0 - m) + expf(l1 - m));
        out[gw * 2] = l0 - lse;
        out[gw * 2 + 1] = l1 - lse;
    }
}

// ---------------- launch ----------------
extern "C" void kernel_launch(void* const* d_in, const int* in_sizes, int n_in,
                              void* d_out, int out_size) {
    const float* x = (const float*)d_in[0];
    const void* ei = d_in[1];
    const void* batch = d_in[2];
    const float* W1 = (const float*)d_in[3];
    const float* asrc1 = (const float*)d_in[4];
    const float* adst1 = (const float*)d_in[5];
    const float* b1 = (const float*)d_in[6];
    const float* W2 = (const float*)d_in[7];
    const float* asrc2 = (const float*)d_in[8];
    const float* adst2 = (const float*)d_in[9];
    const float* b2 = (const float*)d_in[10];
    const float* fcW = (const float*)d_in[11];
    const float* fcb = (const float*)d_in[12];
    float* out = (float*)d_out;

    const int SMEM1 = 128 * 136 * 2 + 128 * 136 * 2 + 128 * 2 * 4;  // 70656
    const int SMEM2 = 128 * 136 * 2 + 64 * 136 * 2 + 64 * 2 * 4;    // 52736

    static cudaStream_t s2 = nullptr;
    static cudaEvent_t evA = nullptr, evB = nullptr;
    static void *p_deg = nullptr, *p_pool = nullptr, *p_cnt = nullptr;
    if (!s2) {
        cudaStreamCreateWithFlags(&s2, cudaStreamNonBlocking);
        cudaEventCreateWithFlags(&evA, cudaEventDisableTiming);
        cudaEventCreateWithFlags(&evB, cudaEventDisableTiming);
        cudaFuncSetAttribute(gemm1_k, cudaFuncAttributeMaxDynamicSharedMemorySize, SMEM1);
        cudaFuncSetAttribute(gemm2_k, cudaFuncAttributeMaxDynamicSharedMemorySize, SMEM2);
        cudaGetSymbolAddress(&p_deg, g_deg);
        cudaGetSymbolAddress(&p_pool, g_pool);
        cudaGetSymbolAddress(&p_cnt, g_cnt);
    }

    // fork: bucket build on s2 (scatter first), gemm1 on main stream
    cudaEventRecord(evA, 0);
    cudaStreamWaitEvent(s2, evA, 0);

    cudaMemsetAsync(p_deg, 0, NN * sizeof(int), s2);
    detect_k<<<1, 512, 0, s2>>>((const uint*)ei);
    scatter_k<<<(NE + 255) / 256, 256, 0, s2>>>(ei);
    cudaMemsetAsync(p_pool, 0, NG * C2 * sizeof(float), s2);
    cudaMemsetAsync(p_cnt, 0, NG * sizeof(float), s2);
    cudaEventRecord(evB, s2);

    gemm1_k<<<(NN + 127) / 128, 256, SMEM1>>>(x, W1, asrc1, adst1);

    cudaStreamWaitEvent(0, evB, 0);

    edge1_k<<<(NN * 32 + 255) / 256, 256>>>(b1);
    gemm2_k<<<(NN + 127) / 128, 256, SMEM2>>>(W2, asrc2, adst2);
    edge2_k<<<(NN * 32 + 255) / 256, 256>>>(b2, batch);
    final_k<<<(NG * 32 + 255) / 256, 256>>>(fcW, fcb, out);
}